// round 4
// baseline (speedup 1.0000x reference)
#include <cuda_runtime.h>
#include <cuda_bf16.h>
#include <cstdint>

// Problem constants (fixed by metadata): B=32, N=300, C=3, H=W=1024
#define BB 32
#define NN 300
#define HH 1024
#define WW 1024
#define NBOX (BB * NN)          // 9600
#define PLANE (1u << 20)        // 1024*1024
#define NCHUNK 8
#define CHROWS (HH / NCHUNK)    // 128 rows per chunk

// Scratch: per-chunk local column-prefix of (class2 - class1). 128 MiB.
__device__ float g_cc[(size_t)BB * PLANE];
// Per-(batch, chunk, col) chunk totals (raw, summed on demand in k_box). 1 MiB.
__device__ float g_tot[BB * NCHUNK * WW];
// Per-batch bitmask of rows of g_cc that box queries will read.
// Invariant: all-zero between kernel_launch calls (static zero-init on load;
// k_box re-zeroes at its head each call -> correct for any input sequence).
__device__ unsigned g_rowmask[BB * 32];

__device__ __forceinline__ int clampi(int v, int lo, int hi) {
    return v < lo ? lo : (v > hi ? hi : v);
}

// trunc-toward-zero then clamp — bit-exact vs the reference.
__device__ __forceinline__ void box_coords(const float* __restrict__ boxes, int i,
                                           int& x1, int& x2, int& y1, int& y2) {
    float cx = boxes[i * 4 + 0];
    float cy = boxes[i * 4 + 1];
    float w  = boxes[i * 4 + 2];
    float h  = boxes[i * 4 + 3];
    x1 = clampi((int)((cx - w * 0.5f) * (float)WW), 0, WW - 1);
    x2 = clampi((int)((cx + w * 0.5f) * (float)WW), 0, WW - 1);
    y1 = clampi((int)((cy - h * 0.5f) * (float)HH), 0, HH - 1);
    y2 = clampi((int)((cy + h * 0.5f) * (float)HH), 0, HH - 1);
}

// Kernel 1: one thread per box — mark needed rows. Also zeros the output
// scalar (thread 0; ordered before k_box's atomics by launch order).
__global__ void k_mark(const float* __restrict__ boxes,
                       const float* __restrict__ conf,
                       float* __restrict__ out) {
    int i = blockIdx.x * blockDim.x + threadIdx.x;
    if (i == 0) out[0] = 0.0f;
    if (i >= NBOX) return;
    int x1, x2, y1, y2;
    box_coords(boxes, i, x1, x2, y1, y2);
    if ((conf[i] >= 0.3f) && (x2 > x1) && (y2 > y1)) {
        int b = i / NN;
        int rt = y2 - 1;
        atomicOr(&g_rowmask[b * 32 + (rt >> 5)], 1u << (rt & 31));
        if (y1 > 0) {
            int rb = y1 - 1;
            atomicOr(&g_rowmask[b * 32 + (rb >> 5)], 1u << (rb & 31));
        }
    }
}

// Kernel 2: segmented column-prefix of diff = seg[b,2] - seg[b,1], float4-wide.
// grid = (2, NCHUNK, BB), block = 128. Each thread scans CHROWS rows of 4
// adjacent columns: stores LOCAL masked prefix rows (STG.128) + chunk totals.
__global__ void k_scan(const float* __restrict__ seg) {
    int b     = blockIdx.z;
    int chunk = blockIdx.y;
    int col4  = blockIdx.x * 128 + threadIdx.x;   // float4 index, 0..255
    int r0    = chunk * CHROWS;

    __shared__ unsigned smask[4];
    if (threadIdx.x < 4)
        smask[threadIdx.x] = g_rowmask[b * 32 + (r0 >> 5) + threadIdx.x];
    __syncthreads();

    const float4* __restrict__ p1 =
        (const float4*)(seg + ((size_t)(b * 3 + 1)) * PLANE + (size_t)r0 * WW) + col4;
    const float4* __restrict__ p2 =
        (const float4*)(seg + ((size_t)(b * 3 + 2)) * PLANE + (size_t)r0 * WW) + col4;
    float4* __restrict__ pc =
        (float4*)(g_cc + ((size_t)b) * PLANE + (size_t)r0 * WW) + col4;
    const int RS = WW / 4;   // row stride in float4

    float4 run = make_float4(0.f, 0.f, 0.f, 0.f);
#pragma unroll
    for (int w = 0; w < 4; ++w) {
        unsigned m = smask[w];
#pragma unroll
        for (int g = 0; g < 8; ++g) {
            float4 a[4], c[4];
#pragma unroll
            for (int i = 0; i < 4; ++i) { a[i] = p1[i * RS]; c[i] = p2[i * RS]; }
#pragma unroll
            for (int i = 0; i < 4; ++i) {
                run.x += c[i].x - a[i].x;
                run.y += c[i].y - a[i].y;
                run.z += c[i].z - a[i].z;
                run.w += c[i].w - a[i].w;
                if ((m >> (g * 4 + i)) & 1u) pc[i * RS] = run;
            }
            p1 += 4 * RS;
            p2 += 4 * RS;
            pc += 4 * RS;
        }
    }
    ((float4*)(g_tot + (b * NCHUNK + chunk) * WW))[col4] = run;
}

// Kernel 3: one block per box. Reduce row segments + chunk totals in [cb,ct),
// relu, weight by confidence, atomicAdd. Also re-zeroes g_rowmask (blocks 0-7)
// to restore the between-calls invariant.
__global__ void k_box(const float* __restrict__ boxes,
                      const float* __restrict__ conf,
                      float* __restrict__ out) {
    if (blockIdx.x < 8) {
        int z = blockIdx.x * 128 + threadIdx.x;   // 0..1023 = BB*32
        g_rowmask[z] = 0u;
    }

    int i = blockIdx.x;
    int x1, x2, y1, y2;
    box_coords(boxes, i, x1, x2, y1, y2);
    float cf = conf[i];
    if (!((cf >= 0.3f) && (x2 > x1) && (y2 > y1))) return;

    int b = i / NN;
    int rt = y2 - 1;
    int ct = rt / CHROWS;
    const float* __restrict__ top = g_cc + ((size_t)b) * PLANE + (size_t)rt * WW;
    const float* __restrict__ tot = g_tot + b * NCHUNK * WW;

    float s = 0.0f;
    int tx = (int)threadIdx.x;
    if (y1 > 0) {
        int rb = y1 - 1;
        int cb = rb / CHROWS;
        const float* __restrict__ bot = g_cc + ((size_t)b) * PLANE + (size_t)rb * WW;
        for (int x = x1 + tx; x < x2; x += (int)blockDim.x) {
            float v = top[x] - bot[x];
            for (int c = cb; c < ct; ++c) v += tot[c * WW + x];
            s += v;
        }
    } else {
        for (int x = x1 + tx; x < x2; x += (int)blockDim.x) {
            float v = top[x];
            for (int c = 0; c < ct; ++c) v += tot[c * WW + x];
            s += v;
        }
    }

    __shared__ float red[4];
#pragma unroll
    for (int off = 16; off > 0; off >>= 1)
        s += __shfl_down_sync(0xFFFFFFFFu, s, off);
    if ((threadIdx.x & 31) == 0) red[threadIdx.x >> 5] = s;
    __syncthreads();
    if (threadIdx.x == 0) {
        float tsum = red[0] + red[1] + red[2] + red[3];
        float area = (float)((y2 - y1) * (x2 - x1));
        float pb = fmaxf(tsum / area, 0.0f) * cf;
        atomicAdd(out, pb * (1.0f / (float)NBOX));
    }
}

extern "C" void kernel_launch(void* const* d_in, const int* in_sizes, int n_in,
                              void* d_out, int out_size) {
    const float* boxes = (const float*)d_in[0];   // (32,300,4)
    const float* conf  = (const float*)d_in[1];   // (32,300)
    const float* seg   = (const float*)d_in[2];   // (32,3,1024,1024)
    float* out = (float*)d_out;

    k_mark<<<(NBOX + 127) / 128, 128>>>(boxes, conf, out);
    dim3 gscan(2, NCHUNK, BB);
    k_scan<<<gscan, 128>>>(seg);
    k_box<<<NBOX, 128>>>(boxes, conf, out);
}

// round 7
// speedup vs baseline: 1.1661x; 1.1661x over previous
#include <cuda_runtime.h>
#include <cuda_bf16.h>
#include <cstdint>

// Problem constants (fixed by metadata): B=32, N=300, C=3, H=W=1024
#define BB 32
#define NN 300
#define HH 1024
#define WW 1024
#define NBOX (BB * NN)          // 9600
#define PLANE (1u << 20)        // 1024*1024
#define NCHUNK 8
#define CHROWS (HH / NCHUNK)    // 128 rows per chunk
#define MASKW (BB * 32)         // rowmask words

// Scratch: per-chunk local column-prefix of (class2 - class1). 128 MiB.
__device__ float g_cc[(size_t)BB * PLANE];
// Per-(batch, chunk, col) chunk totals -> exclusive prefix (offsets). 1 MiB.
__device__ float g_tot[BB * NCHUNK * WW];
// Per-batch bitmask of rows of g_cc that box queries will read.
// Invariant: all-zero between kernel_launch calls (static zero-init on load;
// k_box re-zeroes at its head each call -> correct for any input sequence).
__device__ unsigned g_rowmask[MASKW];

__device__ __forceinline__ int clampi(int v, int lo, int hi) {
    return v < lo ? lo : (v > hi ? hi : v);
}

// trunc-toward-zero then clamp — bit-exact vs the reference.
__device__ __forceinline__ void box_coords(const float* __restrict__ boxes, int i,
                                           int& x1, int& x2, int& y1, int& y2) {
    float cx = boxes[i * 4 + 0];
    float cy = boxes[i * 4 + 1];
    float w  = boxes[i * 4 + 2];
    float h  = boxes[i * 4 + 3];
    x1 = clampi((int)((cx - w * 0.5f) * (float)WW), 0, WW - 1);
    x2 = clampi((int)((cx + w * 0.5f) * (float)WW), 0, WW - 1);
    y1 = clampi((int)((cy - h * 0.5f) * (float)HH), 0, HH - 1);
    y2 = clampi((int)((cy + h * 0.5f) * (float)HH), 0, HH - 1);
}

// Kernel 1: one thread per box — mark needed rows. Thread 0 also zeros the
// output scalar (ordered before k_box's atomics by launch order).
__global__ void k_mark(const float* __restrict__ boxes,
                       const float* __restrict__ conf,
                       float* __restrict__ out) {
    int i = blockIdx.x * blockDim.x + threadIdx.x;
    if (i == 0) out[0] = 0.0f;
    if (i >= NBOX) return;
    int x1, x2, y1, y2;
    box_coords(boxes, i, x1, x2, y1, y2);
    if ((conf[i] >= 0.3f) && (x2 > x1) && (y2 > y1)) {
        int b = i / NN;
        int rt = y2 - 1;
        atomicOr(&g_rowmask[b * 32 + (rt >> 5)], 1u << (rt & 31));
        if (y1 > 0) {
            int rb = y1 - 1;
            atomicOr(&g_rowmask[b * 32 + (rb >> 5)], 1u << (rb & 31));
        }
    }
}

// Kernel 2 (round-3 proven version): segmented column-prefix of
// diff = seg[b,2] - seg[b,1]. grid = (WW/128, NCHUNK, BB), block = 128.
// One column per thread, CHROWS rows; batch-loads 8 row-diffs (independent
// LDGs) before folding into the loop-carried prefix; masked stores only.
__global__ void k_scan(const float* __restrict__ seg) {
    int b     = blockIdx.z;
    int chunk = blockIdx.y;
    int col   = blockIdx.x * 128 + threadIdx.x;
    int r0    = chunk * CHROWS;

    __shared__ unsigned smask[CHROWS / 32];
    if (threadIdx.x < CHROWS / 32)
        smask[threadIdx.x] = g_rowmask[b * 32 + (r0 >> 5) + threadIdx.x];
    __syncthreads();

    const float* __restrict__ p1 = seg + ((size_t)(b * 3 + 1)) * PLANE + (size_t)r0 * WW + col;
    const float* __restrict__ p2 = seg + ((size_t)(b * 3 + 2)) * PLANE + (size_t)r0 * WW + col;
    float* __restrict__ pc = g_cc + ((size_t)b) * PLANE + (size_t)r0 * WW + col;

    float run = 0.0f;
#pragma unroll
    for (int w = 0; w < CHROWS / 32; ++w) {
        unsigned m = smask[w];
#pragma unroll
        for (int g = 0; g < 4; ++g) {
            float d[8];
#pragma unroll
            for (int i = 0; i < 8; ++i)
                d[i] = p2[(size_t)i * WW] - p1[(size_t)i * WW];
#pragma unroll
            for (int i = 0; i < 8; ++i) {
                run += d[i];
                if ((m >> (g * 8 + i)) & 1u) pc[(size_t)i * WW] = run;
            }
            p1 += 8 * WW;
            p2 += 8 * WW;
            pc += 8 * WW;
        }
    }
    g_tot[(b * NCHUNK + chunk) * WW + col] = run;
}

// Kernel 3: chunk totals -> per-column exclusive prefixes, in place.
// Batch-load all 8 values first (independent LDGs, one DRAM round-trip),
// prefix in registers, then store — removes the load/store alias chain.
__global__ void k_offpre() {
    int idx = blockIdx.x * blockDim.x + threadIdx.x;   // 0..BB*WW-1
    int b = idx >> 10;
    int col = idx & (WW - 1);
    float v[NCHUNK];
#pragma unroll
    for (int c = 0; c < NCHUNK; ++c)
        v[c] = g_tot[(b * NCHUNK + c) * WW + col];
    float run = 0.0f;
#pragma unroll
    for (int c = 0; c < NCHUNK; ++c) {
        float t = v[c];
        g_tot[(b * NCHUNK + c) * WW + col] = run;
        run += t;
    }
}

// Kernel 4: one block per box. Reduce row segments (+chunk offsets), relu,
// weight by confidence, atomicAdd. Blocks 0-7 also re-zero g_rowmask to
// restore the between-calls invariant.
__global__ void k_box(const float* __restrict__ boxes,
                      const float* __restrict__ conf,
                      float* __restrict__ out) {
    {
        int z = blockIdx.x * (int)blockDim.x + (int)threadIdx.x;
        if (z < MASKW) g_rowmask[z] = 0u;
    }

    int i = blockIdx.x;
    int x1, x2, y1, y2;
    box_coords(boxes, i, x1, x2, y1, y2);
    float cf = conf[i];
    if (!((cf >= 0.3f) && (x2 > x1) && (y2 > y1))) return;

    int b = i / NN;
    int rt = y2 - 1;
    int ct = rt / CHROWS;
    const float* __restrict__ top  = g_cc + ((size_t)b) * PLANE + (size_t)rt * WW;
    const float* __restrict__ offt = g_tot + (b * NCHUNK + ct) * WW;

    float s = 0.0f;
    int tx = (int)threadIdx.x;
    if (y1 > 0) {
        int rb = y1 - 1;
        int cb = rb / CHROWS;
        const float* __restrict__ bot = g_cc + ((size_t)b) * PLANE + (size_t)rb * WW;
        if (ct == cb) {
            for (int x = x1 + tx; x < x2; x += (int)blockDim.x)
                s += top[x] - bot[x];
        } else {
            const float* __restrict__ offb = g_tot + (b * NCHUNK + cb) * WW;
            for (int x = x1 + tx; x < x2; x += (int)blockDim.x)
                s += (top[x] - bot[x]) + (offt[x] - offb[x]);
        }
    } else {
        if (ct == 0) {
            for (int x = x1 + tx; x < x2; x += (int)blockDim.x)
                s += top[x];
        } else {
            for (int x = x1 + tx; x < x2; x += (int)blockDim.x)
                s += top[x] + offt[x];
        }
    }

    __shared__ float red[4];
#pragma unroll
    for (int off = 16; off > 0; off >>= 1)
        s += __shfl_down_sync(0xFFFFFFFFu, s, off);
    if ((threadIdx.x & 31) == 0) red[threadIdx.x >> 5] = s;
    __syncthreads();
    if (threadIdx.x == 0) {
        float tsum = red[0] + red[1] + red[2] + red[3];
        float area = (float)((y2 - y1) * (x2 - x1));
        float pb = fmaxf(tsum / area, 0.0f) * cf;
        atomicAdd(out, pb * (1.0f / (float)NBOX));
    }
}

extern "C" void kernel_launch(void* const* d_in, const int* in_sizes, int n_in,
                              void* d_out, int out_size) {
    const float* boxes = (const float*)d_in[0];   // (32,300,4)
    const float* conf  = (const float*)d_in[1];   // (32,300)
    const float* seg   = (const float*)d_in[2];   // (32,3,1024,1024)
    float* out = (float*)d_out;

    k_mark<<<(NBOX + 255) / 256, 256>>>(boxes, conf, out);
    dim3 gscan(WW / 128, NCHUNK, BB);
    k_scan<<<gscan, 128>>>(seg);
    k_offpre<<<(BB * WW) / 1024, 1024>>>();
    k_box<<<NBOX, 128>>>(boxes, conf, out);
}

// round 10
// speedup vs baseline: 1.1666x; 1.0004x over previous
#include <cuda_runtime.h>
#include <cuda_bf16.h>
#include <cstdint>

// Problem constants (fixed by metadata): B=32, N=300, C=3, H=W=1024
#define BB 32
#define NN 300
#define HH 1024
#define WW 1024
#define NBOX (BB * NN)          // 9600
#define PLANE (1u << 20)        // 1024*1024
#define NCHUNK 8
#define CHROWS (HH / NCHUNK)    // 128 rows per chunk

// Scratch: per-chunk local column-prefix of (class2 - class1). 128 MiB.
__device__ float s_colpre[(size_t)BB * PLANE];
// Per-(batch, chunk, col) chunk totals -> exclusive prefix (offsets). 1 MiB.
// After kern_offsets, row (b, 0) is all zeros (exclusive prefix) — used as
// the canonical zero row by kern_boxes' unified path.
__device__ float s_chunktot[BB * NCHUNK * WW];

__device__ __forceinline__ int clampi(int v, int lo, int hi) {
    return v < lo ? lo : (v > hi ? hi : v);
}

// trunc-toward-zero then clamp — bit-exact vs the reference.
__device__ __forceinline__ void box_coords(const float* __restrict__ boxes, int i,
                                           int& x1, int& x2, int& y1, int& y2) {
    float cx = boxes[i * 4 + 0];
    float cy = boxes[i * 4 + 1];
    float w  = boxes[i * 4 + 2];
    float h  = boxes[i * 4 + 3];
    x1 = clampi((int)((cx - w * 0.5f) * (float)WW), 0, WW - 1);
    x2 = clampi((int)((cx + w * 0.5f) * (float)WW), 0, WW - 1);
    y1 = clampi((int)((cy - h * 0.5f) * (float)HH), 0, HH - 1);
    y2 = clampi((int)((cy + h * 0.5f) * (float)HH), 0, HH - 1);
}

// Kernel 1: segmented column-prefix of diff = seg[b,2] - seg[b,1].
// grid = (WW/128, NCHUNK, BB), block = 128. Each block first computes its own
// chunk's row mask from the batch's boxes (no separate mark kernel), then
// scans CHROWS rows of one column per thread; masked stores only.
__global__ void __launch_bounds__(128)
kern_colscan(const float* __restrict__ seg,
             const float* __restrict__ boxes,
             const float* __restrict__ conf,
             float* __restrict__ out) {
    const int b     = blockIdx.z;
    const int chunk = blockIdx.y;
    const int col   = blockIdx.x * 128 + threadIdx.x;
    const int r0    = chunk * CHROWS;

    // zero the output scalar once (ordered before kern_boxes' atomics by launch order)
    if ((blockIdx.x | blockIdx.y | blockIdx.z | threadIdx.x) == 0)
        out[0] = 0.0f;

    // Build this chunk's row mask in shared memory from the batch's boxes.
    __shared__ unsigned smask[CHROWS / 32];
    if (threadIdx.x < CHROWS / 32) smask[threadIdx.x] = 0u;
    __syncthreads();
    for (int j = (int)threadIdx.x; j < NN; j += 128) {
        int i = b * NN + j;
        int x1, x2, y1, y2;
        box_coords(boxes, i, x1, x2, y1, y2);
        if ((conf[i] >= 0.3f) && (x2 > x1) && (y2 > y1)) {
            int rt = y2 - 1;
            if ((unsigned)(rt - r0) < (unsigned)CHROWS)
                atomicOr(&smask[(rt - r0) >> 5], 1u << (rt & 31));
            if (y1 > 0) {
                int rb = y1 - 1;
                if ((unsigned)(rb - r0) < (unsigned)CHROWS)
                    atomicOr(&smask[(rb - r0) >> 5], 1u << (rb & 31));
            }
        }
    }
    __syncthreads();

    const float* __restrict__ p1 = seg + ((size_t)(b * 3 + 1)) * PLANE + (size_t)r0 * WW + col;
    const float* __restrict__ p2 = seg + ((size_t)(b * 3 + 2)) * PLANE + (size_t)r0 * WW + col;
    float* __restrict__ pc = s_colpre + ((size_t)b) * PLANE + (size_t)r0 * WW + col;

    float run = 0.0f;
#pragma unroll
    for (int w = 0; w < CHROWS / 32; ++w) {
        unsigned m = smask[w];
#pragma unroll
        for (int g = 0; g < 4; ++g) {
            float d[8];
#pragma unroll
            for (int i = 0; i < 8; ++i)
                d[i] = p2[(size_t)i * WW] - p1[(size_t)i * WW];
#pragma unroll
            for (int i = 0; i < 8; ++i) {
                run += d[i];
                if ((m >> (g * 8 + i)) & 1u) pc[(size_t)i * WW] = run;
            }
            p1 += 8 * WW;
            p2 += 8 * WW;
            pc += 8 * WW;
        }
    }
    s_chunktot[(b * NCHUNK + chunk) * WW + col] = run;
}

// Kernel 2: chunk totals -> per-column exclusive prefixes, in place.
// Batch-load all 8 values (independent LDGs), prefix in registers, store.
__global__ void __launch_bounds__(512)
kern_offsets() {
    int idx = blockIdx.x * 512 + threadIdx.x;   // 0..BB*WW-1
    int b = idx >> 10;
    int col = idx & (WW - 1);
    float v[NCHUNK];
#pragma unroll
    for (int c = 0; c < NCHUNK; ++c)
        v[c] = s_chunktot[(b * NCHUNK + c) * WW + col];
    float run = 0.0f;
#pragma unroll
    for (int c = 0; c < NCHUNK; ++c) {
        float t = v[c];
        s_chunktot[(b * NCHUNK + c) * WW + col] = run;
        run += t;
    }
}

// Kernel 3: one block per box. Unified 4-stream segment reduce with float4
// interior loads: s = (top - bot) + (offt - offb). For y1==0, bot and offb
// both point at s_chunktot[b][0] (zeros after kern_offsets), so one code
// path covers every case. relu, conf weight, atomicAdd into the scalar.
__global__ void __launch_bounds__(128)
kern_boxes(const float* __restrict__ boxes,
           const float* __restrict__ conf,
           float* __restrict__ out) {
    int i = blockIdx.x;
    int x1, x2, y1, y2;
    box_coords(boxes, i, x1, x2, y1, y2);
    float cf = conf[i];
    if (!((cf >= 0.3f) && (x2 > x1) && (y2 > y1))) return;

    int b = i / NN;
    int rt = y2 - 1;
    int ct = rt / CHROWS;
    const float* __restrict__ top  = s_colpre  + ((size_t)b) * PLANE + (size_t)rt * WW;
    const float* __restrict__ offt = s_chunktot + (b * NCHUNK + ct) * WW;
    const float* __restrict__ bot;
    const float* __restrict__ offb;
    if (y1 > 0) {
        int rb = y1 - 1;
        int cb = rb / CHROWS;
        bot  = s_colpre  + ((size_t)b) * PLANE + (size_t)rb * WW;
        offb = s_chunktot + (b * NCHUNK + cb) * WW;
    } else {
        bot  = s_chunktot + b * NCHUNK * WW;   // chunk-0 offset row: zeros
        offb = bot;
    }

    float s = 0.0f;
    int tx = (int)threadIdx.x;
    int xa = (x1 + 3) & ~3;   // first float4-aligned pixel
    int xb = x2 & ~3;         // end of float4 region
    if (xa >= xb) {
        // narrow box: plain scalar
        for (int x = x1 + tx; x < x2; x += 128)
            s += (top[x] - bot[x]) + (offt[x] - offb[x]);
    } else {
        // scalar edges (<= 3 + 3 elements) on low threads
        int ne1 = xa - x1;
        int ne2 = x2 - xb;
        if (tx < ne1) {
            int x = x1 + tx;
            s += (top[x] - bot[x]) + (offt[x] - offb[x]);
        } else if (tx < ne1 + ne2) {
            int x = xb + (tx - ne1);
            s += (top[x] - bot[x]) + (offt[x] - offb[x]);
        }
        // float4 interior
        const float4* t4 = (const float4*)top;
        const float4* b4 = (const float4*)bot;
        const float4* ot4 = (const float4*)offt;
        const float4* ob4 = (const float4*)offb;
        for (int q = xa / 4 + tx; q < xb / 4; q += 128) {
            float4 a = t4[q], c = b4[q], u = ot4[q], v = ob4[q];
            s += (a.x - c.x) + (u.x - v.x);
            s += (a.y - c.y) + (u.y - v.y);
            s += (a.z - c.z) + (u.z - v.z);
            s += (a.w - c.w) + (u.w - v.w);
        }
    }

    __shared__ float red[4];
#pragma unroll
    for (int off = 16; off > 0; off >>= 1)
        s += __shfl_down_sync(0xFFFFFFFFu, s, off);
    if ((threadIdx.x & 31) == 0) red[threadIdx.x >> 5] = s;
    __syncthreads();
    if (threadIdx.x == 0) {
        float tsum = red[0] + red[1] + red[2] + red[3];
        float area = (float)((y2 - y1) * (x2 - x1));
        float pb = fmaxf(tsum / area, 0.0f) * cf;
        atomicAdd(out, pb * (1.0f / (float)NBOX));
    }
}

extern "C" void kernel_launch(void* const* d_in, const int* in_sizes, int n_in,
                              void* d_out, int out_size) {
    const float* boxes = (const float*)d_in[0];   // (32,300,4)
    const float* conf  = (const float*)d_in[1];   // (32,300)
    const float* seg   = (const float*)d_in[2];   // (32,3,1024,1024)
    float* out = (float*)d_out;

    dim3 gscan(WW / 128, NCHUNK, BB);
    kern_colscan<<<gscan, 128>>>(seg, boxes, conf, out);
    kern_offsets<<<(BB * WW) / 512, 512>>>();
    kern_boxes<<<NBOX, 128>>>(boxes, conf, out);
}

// round 13
// speedup vs baseline: 1.2494x; 1.0710x over previous
#include <cuda_runtime.h>
#include <cuda_bf16.h>
#include <cstdint>

// Problem constants (fixed by metadata): B=32, N=300, C=3, H=W=1024
#define BB 32
#define NN 300
#define HH 1024
#define WW 1024
#define NBOX (BB * NN)          // 9600
#define PLANE (1u << 20)        // 1024*1024
#define NCHUNK 8
#define CHROWS (HH / NCHUNK)    // 128 rows per chunk

// Scratch: per-chunk local column-prefix of (class2 - class1). 128 MiB.
__device__ float s_colpre[(size_t)BB * PLANE];
// Per-(batch, chunk, col) chunk totals -> exclusive prefix (offsets). 1 MiB.
// After kern_offsets, row (b, 0) is all zeros (exclusive prefix) — used as
// the canonical zero row by kern_boxes' unified path.
__device__ float s_chunktot[BB * NCHUNK * WW];

__device__ __forceinline__ int clampi(int v, int lo, int hi) {
    return v < lo ? lo : (v > hi ? hi : v);
}

// trunc-toward-zero then clamp — bit-exact vs the reference.
__device__ __forceinline__ void box_coords(const float* __restrict__ boxes, int i,
                                           int& x1, int& x2, int& y1, int& y2) {
    float cx = boxes[i * 4 + 0];
    float cy = boxes[i * 4 + 1];
    float w  = boxes[i * 4 + 2];
    float h  = boxes[i * 4 + 3];
    x1 = clampi((int)((cx - w * 0.5f) * (float)WW), 0, WW - 1);
    x2 = clampi((int)((cx + w * 0.5f) * (float)WW), 0, WW - 1);
    y1 = clampi((int)((cy - h * 0.5f) * (float)HH), 0, HH - 1);
    y2 = clampi((int)((cy + h * 0.5f) * (float)HH), 0, HH - 1);
}

// Kernel 1: segmented column-prefix of diff = seg[b,2] - seg[b,1].
// grid = (WW/128, NCHUNK, BB), block = 128. Each block first computes its own
// chunk's row mask from the batch's boxes, then scans CHROWS rows of one
// column per thread; masked stores only. seg is read with .cs (evict-first):
// it has zero reuse, and keeping it out of L2 leaves the s_colpre writes
// L2-resident for kern_boxes. Inner loop front-batches only 4 rows (8 LDGs)
// to limit cross-CTA L1tex-queue contention (B300 spread model).
__global__ void __launch_bounds__(128)
kern_colscan(const float* __restrict__ seg,
             const float* __restrict__ boxes,
             const float* __restrict__ conf,
             float* __restrict__ out) {
    const int b     = blockIdx.z;
    const int chunk = blockIdx.y;
    const int col   = blockIdx.x * 128 + threadIdx.x;
    const int r0    = chunk * CHROWS;

    // zero the output scalar once (ordered before kern_boxes' atomics by launch order)
    if ((blockIdx.x | blockIdx.y | blockIdx.z | threadIdx.x) == 0)
        out[0] = 0.0f;

    // Build this chunk's row mask in shared memory from the batch's boxes.
    __shared__ unsigned smask[CHROWS / 32];
    if (threadIdx.x < CHROWS / 32) smask[threadIdx.x] = 0u;
    __syncthreads();
    for (int j = (int)threadIdx.x; j < NN; j += 128) {
        int i = b * NN + j;
        int x1, x2, y1, y2;
        box_coords(boxes, i, x1, x2, y1, y2);
        if ((conf[i] >= 0.3f) && (x2 > x1) && (y2 > y1)) {
            int rt = y2 - 1;
            if ((unsigned)(rt - r0) < (unsigned)CHROWS)
                atomicOr(&smask[(rt - r0) >> 5], 1u << (rt & 31));
            if (y1 > 0) {
                int rb = y1 - 1;
                if ((unsigned)(rb - r0) < (unsigned)CHROWS)
                    atomicOr(&smask[(rb - r0) >> 5], 1u << (rb & 31));
            }
        }
    }
    __syncthreads();

    const float* __restrict__ p1 = seg + ((size_t)(b * 3 + 1)) * PLANE + (size_t)r0 * WW + col;
    const float* __restrict__ p2 = seg + ((size_t)(b * 3 + 2)) * PLANE + (size_t)r0 * WW + col;
    float* __restrict__ pc = s_colpre + ((size_t)b) * PLANE + (size_t)r0 * WW + col;

    float run = 0.0f;
#pragma unroll
    for (int w = 0; w < CHROWS / 32; ++w) {
        unsigned m = smask[w];
#pragma unroll
        for (int g = 0; g < 8; ++g) {
            float a[4], c[4];
#pragma unroll
            for (int i = 0; i < 4; ++i) {
                a[i] = __ldcs(p1 + (size_t)i * WW);
                c[i] = __ldcs(p2 + (size_t)i * WW);
            }
#pragma unroll
            for (int i = 0; i < 4; ++i) {
                run += c[i] - a[i];
                if ((m >> (g * 4 + i)) & 1u) pc[(size_t)i * WW] = run;
            }
            p1 += 4 * WW;
            p2 += 4 * WW;
            pc += 4 * WW;
        }
    }
    s_chunktot[(b * NCHUNK + chunk) * WW + col] = run;
}

// Kernel 2: chunk totals -> per-column exclusive prefixes, in place.
// Batch-load all 8 values (independent LDGs), prefix in registers, store.
__global__ void __launch_bounds__(512)
kern_offsets() {
    int idx = blockIdx.x * 512 + threadIdx.x;   // 0..BB*WW-1
    int b = idx >> 10;
    int col = idx & (WW - 1);
    float v[NCHUNK];
#pragma unroll
    for (int c = 0; c < NCHUNK; ++c)
        v[c] = s_chunktot[(b * NCHUNK + c) * WW + col];
    float run = 0.0f;
#pragma unroll
    for (int c = 0; c < NCHUNK; ++c) {
        float t = v[c];
        s_chunktot[(b * NCHUNK + c) * WW + col] = run;
        run += t;
    }
}

// Kernel 3: one block per box. Unified 4-stream segment reduce with float4
// interior loads: s = (top - bot) + (offt - offb). For y1==0, bot and offb
// both point at s_chunktot[b][0] (zeros after kern_offsets), so one code
// path covers every case. relu, conf weight, atomicAdd into the scalar.
__global__ void __launch_bounds__(128)
kern_boxes(const float* __restrict__ boxes,
           const float* __restrict__ conf,
           float* __restrict__ out) {
    int i = blockIdx.x;
    int x1, x2, y1, y2;
    box_coords(boxes, i, x1, x2, y1, y2);
    float cf = conf[i];
    if (!((cf >= 0.3f) && (x2 > x1) && (y2 > y1))) return;

    int b = i / NN;
    int rt = y2 - 1;
    int ct = rt / CHROWS;
    const float* __restrict__ top  = s_colpre  + ((size_t)b) * PLANE + (size_t)rt * WW;
    const float* __restrict__ offt = s_chunktot + (b * NCHUNK + ct) * WW;
    const float* __restrict__ bot;
    const float* __restrict__ offb;
    if (y1 > 0) {
        int rb = y1 - 1;
        int cb = rb / CHROWS;
        bot  = s_colpre  + ((size_t)b) * PLANE + (size_t)rb * WW;
        offb = s_chunktot + (b * NCHUNK + cb) * WW;
    } else {
        bot  = s_chunktot + b * NCHUNK * WW;   // chunk-0 offset row: zeros
        offb = bot;
    }

    float s = 0.0f;
    int tx = (int)threadIdx.x;
    int xa = (x1 + 3) & ~3;   // first float4-aligned pixel
    int xb = x2 & ~3;         // end of float4 region
    if (xa >= xb) {
        // narrow box: plain scalar
        for (int x = x1 + tx; x < x2; x += 128)
            s += (top[x] - bot[x]) + (offt[x] - offb[x]);
    } else {
        // scalar edges (<= 3 + 3 elements) on low threads
        int ne1 = xa - x1;
        int ne2 = x2 - xb;
        if (tx < ne1) {
            int x = x1 + tx;
            s += (top[x] - bot[x]) + (offt[x] - offb[x]);
        } else if (tx < ne1 + ne2) {
            int x = xb + (tx - ne1);
            s += (top[x] - bot[x]) + (offt[x] - offb[x]);
        }
        // float4 interior
        const float4* t4 = (const float4*)top;
        const float4* b4 = (const float4*)bot;
        const float4* ot4 = (const float4*)offt;
        const float4* ob4 = (const float4*)offb;
        for (int q = xa / 4 + tx; q < xb / 4; q += 128) {
            float4 a = t4[q], c = b4[q], u = ot4[q], v = ob4[q];
            s += (a.x - c.x) + (u.x - v.x);
            s += (a.y - c.y) + (u.y - v.y);
            s += (a.z - c.z) + (u.z - v.z);
            s += (a.w - c.w) + (u.w - v.w);
        }
    }

    __shared__ float red[4];
#pragma unroll
    for (int off = 16; off > 0; off >>= 1)
        s += __shfl_down_sync(0xFFFFFFFFu, s, off);
    if ((threadIdx.x & 31) == 0) red[threadIdx.x >> 5] = s;
    __syncthreads();
    if (threadIdx.x == 0) {
        float tsum = red[0] + red[1] + red[2] + red[3];
        float area = (float)((y2 - y1) * (x2 - x1));
        float pb = fmaxf(tsum / area, 0.0f) * cf;
        atomicAdd(out, pb * (1.0f / (float)NBOX));
    }
}

extern "C" void kernel_launch(void* const* d_in, const int* in_sizes, int n_in,
                              void* d_out, int out_size) {
    const float* boxes = (const float*)d_in[0];   // (32,300,4)
    const float* conf  = (const float*)d_in[1];   // (32,300)
    const float* seg   = (const float*)d_in[2];   // (32,3,1024,1024)
    float* out = (float*)d_out;

    dim3 gscan(WW / 128, NCHUNK, BB);
    kern_colscan<<<gscan, 128>>>(seg, boxes, conf, out);
    kern_offsets<<<(BB * WW) / 512, 512>>>();
    kern_boxes<<<NBOX, 128>>>(boxes, conf, out);
}

// round 15
// speedup vs baseline: 1.2884x; 1.0312x over previous
#include <cuda_runtime.h>
#include <cuda_bf16.h>
#include <cstdint>

// Problem constants (fixed by metadata): B=32, N=300, C=3, H=W=1024
#define BB 32
#define NN 300
#define HH 1024
#define WW 1024
#define NBOX (BB * NN)          // 9600
#define PLANE (1u << 20)        // 1024*1024
#define NCHUNK 8
#define CHROWS (HH / NCHUNK)    // 128 rows per chunk

// Scratch: per-chunk local column-prefix of (class2 - class1). 128 MiB.
__device__ float s_colpre[(size_t)BB * PLANE];
// Per-(batch, chunk, col) chunk totals -> exclusive prefix (offsets). 1 MiB.
// After kern_offsets, row (b, 0) is all zeros (exclusive prefix) — used as
// the canonical zero row by kern_boxes' unified path.
__device__ float s_chunktot[BB * NCHUNK * WW];

__device__ __forceinline__ int clampi(int v, int lo, int hi) {
    return v < lo ? lo : (v > hi ? hi : v);
}

// trunc-toward-zero then clamp — bit-exact vs the reference.
__device__ __forceinline__ void box_coords(const float* __restrict__ boxes, int i,
                                           int& x1, int& x2, int& y1, int& y2) {
    float cx = boxes[i * 4 + 0];
    float cy = boxes[i * 4 + 1];
    float w  = boxes[i * 4 + 2];
    float h  = boxes[i * 4 + 3];
    x1 = clampi((int)((cx - w * 0.5f) * (float)WW), 0, WW - 1);
    x2 = clampi((int)((cx + w * 0.5f) * (float)WW), 0, WW - 1);
    y1 = clampi((int)((cy - h * 0.5f) * (float)HH), 0, HH - 1);
    y2 = clampi((int)((cy + h * 0.5f) * (float)HH), 0, HH - 1);
}

// Kernel 1: segmented column-prefix of diff = seg[b,2] - seg[b,1].
// grid = (WW/128, NCHUNK, BB), block = 128. Each block computes a row mask
// restricted to ITS OWN 128-column window: a box marks its rows here only if
// its x-range [x1,x2) overlaps [c0,c0+128) — kern_boxes never reads outside
// the box's x-range, so skipping non-overlapped column blocks cuts the
// prefix-write LTS traffic ~2.5x (the scan is LTS-cap-bound, not DRAM-bound).
// seg is read with .cs (evict-first, zero reuse); chunk totals are computed
// unconditionally so kern_offsets is unaffected.
__global__ void __launch_bounds__(128)
kern_colscan(const float* __restrict__ seg,
             const float* __restrict__ boxes,
             const float* __restrict__ conf,
             float* __restrict__ out) {
    const int b     = blockIdx.z;
    const int chunk = blockIdx.y;
    const int c0    = blockIdx.x * 128;
    const int col   = c0 + threadIdx.x;
    const int r0    = chunk * CHROWS;

    // zero the output scalar once (ordered before kern_boxes' atomics by launch order)
    if ((blockIdx.x | blockIdx.y | blockIdx.z | threadIdx.x) == 0)
        out[0] = 0.0f;

    // Build this (chunk, column-window) row mask from the batch's boxes.
    __shared__ unsigned smask[CHROWS / 32];
    if (threadIdx.x < CHROWS / 32) smask[threadIdx.x] = 0u;
    __syncthreads();
    for (int j = (int)threadIdx.x; j < NN; j += 128) {
        int i = b * NN + j;
        int x1, x2, y1, y2;
        box_coords(boxes, i, x1, x2, y1, y2);
        if ((conf[i] >= 0.3f) && (x2 > x1) && (y2 > y1) &&
            (x1 < c0 + 128) && (x2 > c0)) {
            int rt = y2 - 1;
            if ((unsigned)(rt - r0) < (unsigned)CHROWS)
                atomicOr(&smask[(rt - r0) >> 5], 1u << (rt & 31));
            if (y1 > 0) {
                int rb = y1 - 1;
                if ((unsigned)(rb - r0) < (unsigned)CHROWS)
                    atomicOr(&smask[(rb - r0) >> 5], 1u << (rb & 31));
            }
        }
    }
    __syncthreads();

    const float* __restrict__ p1 = seg + ((size_t)(b * 3 + 1)) * PLANE + (size_t)r0 * WW + col;
    const float* __restrict__ p2 = seg + ((size_t)(b * 3 + 2)) * PLANE + (size_t)r0 * WW + col;
    float* __restrict__ pc = s_colpre + ((size_t)b) * PLANE + (size_t)r0 * WW + col;

    float run = 0.0f;
#pragma unroll
    for (int w = 0; w < CHROWS / 32; ++w) {
        unsigned m = smask[w];
#pragma unroll
        for (int g = 0; g < 8; ++g) {
            float a[4], c[4];
#pragma unroll
            for (int i = 0; i < 4; ++i) {
                a[i] = __ldcs(p1 + (size_t)i * WW);
                c[i] = __ldcs(p2 + (size_t)i * WW);
            }
#pragma unroll
            for (int i = 0; i < 4; ++i) {
                run += c[i] - a[i];
                if ((m >> (g * 4 + i)) & 1u) pc[(size_t)i * WW] = run;
            }
            p1 += 4 * WW;
            p2 += 4 * WW;
            pc += 4 * WW;
        }
    }
    s_chunktot[(b * NCHUNK + chunk) * WW + col] = run;
}

// Kernel 2: chunk totals -> per-column exclusive prefixes, in place.
// Batch-load all 8 values (independent LDGs), prefix in registers, store.
__global__ void __launch_bounds__(512)
kern_offsets() {
    int idx = blockIdx.x * 512 + threadIdx.x;   // 0..BB*WW-1
    int b = idx >> 10;
    int col = idx & (WW - 1);
    float v[NCHUNK];
#pragma unroll
    for (int c = 0; c < NCHUNK; ++c)
        v[c] = s_chunktot[(b * NCHUNK + c) * WW + col];
    float run = 0.0f;
#pragma unroll
    for (int c = 0; c < NCHUNK; ++c) {
        float t = v[c];
        s_chunktot[(b * NCHUNK + c) * WW + col] = run;
        run += t;
    }
}

// Kernel 3: one block per box. Unified 4-stream segment reduce with float4
// interior loads: s = (top - bot) + (offt - offb). For y1==0, bot and offb
// both point at s_chunktot[b][0] (zeros after kern_offsets), so one code
// path covers every case. relu, conf weight, atomicAdd into the scalar.
__global__ void __launch_bounds__(128)
kern_boxes(const float* __restrict__ boxes,
           const float* __restrict__ conf,
           float* __restrict__ out) {
    int i = blockIdx.x;
    int x1, x2, y1, y2;
    box_coords(boxes, i, x1, x2, y1, y2);
    float cf = conf[i];
    if (!((cf >= 0.3f) && (x2 > x1) && (y2 > y1))) return;

    int b = i / NN;
    int rt = y2 - 1;
    int ct = rt / CHROWS;
    const float* __restrict__ top  = s_colpre  + ((size_t)b) * PLANE + (size_t)rt * WW;
    const float* __restrict__ offt = s_chunktot + (b * NCHUNK + ct) * WW;
    const float* __restrict__ bot;
    const float* __restrict__ offb;
    if (y1 > 0) {
        int rb = y1 - 1;
        int cb = rb / CHROWS;
        bot  = s_colpre  + ((size_t)b) * PLANE + (size_t)rb * WW;
        offb = s_chunktot + (b * NCHUNK + cb) * WW;
    } else {
        bot  = s_chunktot + b * NCHUNK * WW;   // chunk-0 offset row: zeros
        offb = bot;
    }

    float s = 0.0f;
    int tx = (int)threadIdx.x;
    int xa = (x1 + 3) & ~3;   // first float4-aligned pixel
    int xb = x2 & ~3;         // end of float4 region
    if (xa >= xb) {
        // narrow box: plain scalar
        for (int x = x1 + tx; x < x2; x += 128)
            s += (top[x] - bot[x]) + (offt[x] - offb[x]);
    } else {
        // scalar edges (<= 3 + 3 elements) on low threads
        int ne1 = xa - x1;
        int ne2 = x2 - xb;
        if (tx < ne1) {
            int x = x1 + tx;
            s += (top[x] - bot[x]) + (offt[x] - offb[x]);
        } else if (tx < ne1 + ne2) {
            int x = xb + (tx - ne1);
            s += (top[x] - bot[x]) + (offt[x] - offb[x]);
        }
        // float4 interior
        const float4* t4 = (const float4*)top;
        const float4* b4 = (const float4*)bot;
        const float4* ot4 = (const float4*)offt;
        const float4* ob4 = (const float4*)offb;
        for (int q = xa / 4 + tx; q < xb / 4; q += 128) {
            float4 a = t4[q], c = b4[q], u = ot4[q], v = ob4[q];
            s += (a.x - c.x) + (u.x - v.x);
            s += (a.y - c.y) + (u.y - v.y);
            s += (a.z - c.z) + (u.z - v.z);
            s += (a.w - c.w) + (u.w - v.w);
        }
    }

    __shared__ float red[4];
#pragma unroll
    for (int off = 16; off > 0; off >>= 1)
        s += __shfl_down_sync(0xFFFFFFFFu, s, off);
    if ((threadIdx.x & 31) == 0) red[threadIdx.x >> 5] = s;
    __syncthreads();
    if (threadIdx.x == 0) {
        float tsum = red[0] + red[1] + red[2] + red[3];
        float area = (float)((y2 - y1) * (x2 - x1));
        float pb = fmaxf(tsum / area, 0.0f) * cf;
        atomicAdd(out, pb * (1.0f / (float)NBOX));
    }
}

extern "C" void kernel_launch(void* const* d_in, const int* in_sizes, int n_in,
                              void* d_out, int out_size) {
    const float* boxes = (const float*)d_in[0];   // (32,300,4)
    const float* conf  = (const float*)d_in[1];   // (32,300)
    const float* seg   = (const float*)d_in[2];   // (32,3,1024,1024)
    float* out = (float*)d_out;

    dim3 gscan(WW / 128, NCHUNK, BB);
    kern_colscan<<<gscan, 128>>>(seg, boxes, conf, out);
    kern_offsets<<<(BB * WW) / 512, 512>>>();
    kern_boxes<<<NBOX, 128>>>(boxes, conf, out);
}